// round 2
// baseline (speedup 1.0000x reference)
#include <cuda_runtime.h>

#define BB 1024
#define DD 256
#define MAXN 262144

// Scratch (allocation-free rule: device globals)
__device__ float g_vn_pre[BB * DD];   // pooled means, pre-projection
__device__ int   g_counts[BB];
__device__ int   g_starts[BB];

// ---------------------------------------------------------------------------
// K0: zero counts/starts (must reset every replay of the captured graph)
// ---------------------------------------------------------------------------
__global__ void k_init() {
    int i = blockIdx.x * blockDim.x + threadIdx.x;
    if (i < BB) { g_counts[i] = 0; g_starts[i] = 0; }
}

// ---------------------------------------------------------------------------
// K1: batch is sorted -> mark segment starts, count via gmem atomics (REDG)
// ---------------------------------------------------------------------------
__global__ void k_bounds(const int* __restrict__ batch, int n) {
    int i = blockIdx.x * blockDim.x + threadIdx.x;
    if (i < n) {
        int b = batch[i];
        atomicAdd(&g_counts[b], 1);
        if (i == 0 || batch[i - 1] != b) g_starts[b] = i;
    }
}

// ---------------------------------------------------------------------------
// K2: segment mean. One block per graph; thread t owns column t.
// Warp covers 128B of a row -> fully coalesced. 4 accumulators for load MLP.
// ---------------------------------------------------------------------------
__global__ void k_pool(const float* __restrict__ x) {
    int b = blockIdx.x;
    int t = threadIdx.x;
    int start = g_starts[b];
    int cnt   = g_counts[b];

    float a0 = 0.f, a1 = 0.f, a2 = 0.f, a3 = 0.f;
    const float* p = x + (size_t)start * DD + t;
    int r = 0;
    for (; r + 4 <= cnt; r += 4) {
        a0 += p[0];
        a1 += p[DD];
        a2 += p[2 * DD];
        a3 += p[3 * DD];
        p += 4 * DD;
    }
    for (; r < cnt; r++) { a0 += p[0]; p += DD; }

    float inv = 1.f / (float)max(cnt, 1);
    g_vn_pre[b * DD + t] = ((a0 + a1) + (a2 + a3)) * inv;
}

// ---------------------------------------------------------------------------
// K3: vn = vn_pre @ W^T + bias.  C[m][n] = sum_k A[m][k] * W[n][k].
// 64x64 block tile, TK=16, 4x4 register micro-tile per thread (256 threads).
// Smem stored [k][m] with +1 pad: conflict-free, inner reads broadcast well.
// Writes straight into the d_out tail (vn output region).
// ---------------------------------------------------------------------------
#define TM 64
#define TN 64
#define TK 16

__global__ void k_gemm(const float* __restrict__ W,
                       const float* __restrict__ bias,
                       float* __restrict__ vn_out) {
    __shared__ float As[TK][TM + 1];
    __shared__ float Ws[TK][TN + 1];

    int bm = blockIdx.x * TM;       // 16 blocks over M=1024
    int bn = blockIdx.y * TN;       // 4 blocks over N=256
    int tid = threadIdx.x;          // 256 threads
    int tm = (tid & 15) * 4;        // 0..60
    int tn = (tid >> 4) * 4;        // 0..60

    // loaders: each thread fetches one float4 along K for one row
    int lm = tid >> 2;              // 0..63
    int lk = (tid & 3) * 4;         // 0,4,8,12

    float acc[4][4] = {};

    for (int k0 = 0; k0 < DD; k0 += TK) {
        float4 av = *(const float4*)&g_vn_pre[(size_t)(bm + lm) * DD + k0 + lk];
        As[lk + 0][lm] = av.x; As[lk + 1][lm] = av.y;
        As[lk + 2][lm] = av.z; As[lk + 3][lm] = av.w;
        float4 wv = *(const float4*)&W[(size_t)(bn + lm) * DD + k0 + lk];
        Ws[lk + 0][lm] = wv.x; Ws[lk + 1][lm] = wv.y;
        Ws[lk + 2][lm] = wv.z; Ws[lk + 3][lm] = wv.w;
        __syncthreads();

#pragma unroll
        for (int k = 0; k < TK; k++) {
            float a0 = As[k][tm + 0], a1 = As[k][tm + 1];
            float a2 = As[k][tm + 2], a3 = As[k][tm + 3];
            float w0 = Ws[k][tn + 0], w1 = Ws[k][tn + 1];
            float w2 = Ws[k][tn + 2], w3 = Ws[k][tn + 3];
            acc[0][0] += a0 * w0; acc[0][1] += a0 * w1; acc[0][2] += a0 * w2; acc[0][3] += a0 * w3;
            acc[1][0] += a1 * w0; acc[1][1] += a1 * w1; acc[1][2] += a1 * w2; acc[1][3] += a1 * w3;
            acc[2][0] += a2 * w0; acc[2][1] += a2 * w1; acc[2][2] += a2 * w2; acc[2][3] += a2 * w3;
            acc[3][0] += a3 * w0; acc[3][1] += a3 * w1; acc[3][2] += a3 * w2; acc[3][3] += a3 * w3;
        }
        __syncthreads();
    }

#pragma unroll
    for (int i = 0; i < 4; i++) {
        float4 o;
        o.x = acc[i][0] + bias[bn + tn + 0];
        o.y = acc[i][1] + bias[bn + tn + 1];
        o.z = acc[i][2] + bias[bn + tn + 2];
        o.w = acc[i][3] + bias[bn + tn + 3];
        *(float4*)&vn_out[(size_t)(bm + tm + i) * DD + bn + tn] = o;
    }
}

// ---------------------------------------------------------------------------
// K4: x_out = x + vn[batch].  float4 grid-stride over N*D/4; vn (1 MB) is
// L2-resident, batch row index shared by 64 consecutive threads (L1 hit).
// ---------------------------------------------------------------------------
__global__ void k_add(const float* __restrict__ x,
                      const int* __restrict__ batch,
                      const float* __restrict__ vn,
                      float* __restrict__ out, size_t n4) {
    size_t stride = (size_t)gridDim.x * blockDim.x;
    for (size_t i = (size_t)blockIdx.x * blockDim.x + threadIdx.x; i < n4; i += stride) {
        int row = (int)(i >> 6);   // 64 float4 per 256-float row
        int c4  = (int)(i & 63);
        int b = batch[row];
        float4 xv = ((const float4*)x)[i];
        float4 vv = ((const float4*)vn)[(size_t)b * 64 + c4];
        xv.x += vv.x; xv.y += vv.y; xv.z += vv.z; xv.w += vv.w;
        ((float4*)out)[i] = xv;
    }
}

// ---------------------------------------------------------------------------
extern "C" void kernel_launch(void* const* d_in, const int* in_sizes, int n_in,
                              void* d_out, int out_size) {
    const float* x     = (const float*)d_in[0];   // [N, D]
    const int*   batch = (const int*)d_in[1];     // [N]
    const float* W     = (const float*)d_in[2];   // [D, D]
    const float* bias  = (const float*)d_in[3];   // [D]
    // d_in[4] = layer_idx, unused

    int n = in_sizes[1];                          // number of nodes
    float* out    = (float*)d_out;                // x_out at [0, N*D)
    float* vn_out = out + (size_t)n * DD;         // vn at [N*D, N*D + B*D)

    size_t n4 = (size_t)n * (DD / 4);

    k_init  <<<1, BB>>>();
    k_bounds<<<(n + 255) / 256, 256>>>(batch, n);
    k_pool  <<<BB, 256>>>(x);
    k_gemm  <<<dim3(16, 4), 256>>>(W, bias, vn_out);
    int add_blocks = (int)((n4 + 255) / 256);
    if (add_blocks > 65535 * 8) add_blocks = 65535 * 8;
    k_add   <<<add_blocks, 256>>>(x, batch, vn_out, out, n4);
}

// round 5
// speedup vs baseline: 1.1903x; 1.1903x over previous
#include <cuda_runtime.h>

#define BB 1024
#define DD 256

// Scratch (allocation-free rule: device global)
__device__ float g_vn_pre[BB * DD];   // pooled means, pre-projection

// ---------------------------------------------------------------------------
// K1: segment mean. One block per graph. batch is sorted, so thread 0 finds
// [lo,hi) with two interleaved binary searches, broadcast via smem.
// Thread layout: 64 float4 lanes x 4 row-groups.
// ---------------------------------------------------------------------------
__global__ void k_pool(const float* __restrict__ x,
                       const int* __restrict__ batch, int n) {
    int b = blockIdx.x;
    __shared__ int s_lo, s_hi;

    if (threadIdx.x == 0) {
        // interleaved lower_bound(b) and lower_bound(b+1)
        int lo1 = 0, hi1 = n, lo2 = 0, hi2 = n;
        int v1 = b, v2 = b + 1;
        while ((lo1 < hi1) || (lo2 < hi2)) {
            if (lo1 < hi1) { int m = (lo1 + hi1) >> 1; if (batch[m] < v1) lo1 = m + 1; else hi1 = m; }
            if (lo2 < hi2) { int m = (lo2 + hi2) >> 1; if (batch[m] < v2) lo2 = m + 1; else hi2 = m; }
        }
        s_lo = lo1; s_hi = lo2;
    }
    __syncthreads();
    int lo = s_lo, hi = s_hi;
    int cnt = hi - lo;

    int t    = threadIdx.x;
    int rgrp = t >> 6;        // 0..3
    int c4   = t & 63;        // float4 column

    const float4* xr = (const float4*)x;
    float4 a0 = make_float4(0.f, 0.f, 0.f, 0.f);
    float4 a1 = make_float4(0.f, 0.f, 0.f, 0.f);

    int r = lo + rgrp;
    for (; r + 4 < hi; r += 8) {
        float4 u = xr[(size_t)r * 64 + c4];
        float4 v = xr[(size_t)(r + 4) * 64 + c4];
        a0.x += u.x; a0.y += u.y; a0.z += u.z; a0.w += u.w;
        a1.x += v.x; a1.y += v.y; a1.z += v.z; a1.w += v.w;
    }
    if (r < hi) {
        float4 u = xr[(size_t)r * 64 + c4];
        a0.x += u.x; a0.y += u.y; a0.z += u.z; a0.w += u.w;
    }
    a0.x += a1.x; a0.y += a1.y; a0.z += a1.z; a0.w += a1.w;

    __shared__ float4 red[4][64];
    red[rgrp][c4] = a0;
    __syncthreads();

    if (t < 64) {
        float4 s0 = red[0][t], s1 = red[1][t], s2 = red[2][t], s3 = red[3][t];
        float inv = 1.f / (float)max(cnt, 1);
        float4 o;
        o.x = (s0.x + s1.x + s2.x + s3.x) * inv;
        o.y = (s0.y + s1.y + s2.y + s3.y) * inv;
        o.z = (s0.z + s1.z + s2.z + s3.z) * inv;
        o.w = (s0.w + s1.w + s2.w + s3.w) * inv;
        ((float4*)g_vn_pre)[(size_t)b * 64 + t] = o;
    }
}

// ---------------------------------------------------------------------------
// K2: vn = vn_pre @ W^T + bias.  64x32 block tile (M x N), TK=32,
// 4x2 micro-tile, 256 threads, grid (16, 8) = 128 blocks (fills the chip).
// Smem [k][m] with pad multiple of 4 so LDS.128 stays aligned.
// ---------------------------------------------------------------------------
#define GTM 64
#define GTN 32
#define GTK 32

__global__ void k_gemm(const float* __restrict__ W,
                       const float* __restrict__ bias,
                       float* __restrict__ vn_out) {
    __shared__ float As[GTK][GTM + 4];   // [k][m], pitch 272B = 16B multiple
    __shared__ float Ws[GTK][GTN + 4];   // [k][n], pitch 144B

    int bm = blockIdx.x * GTM;           // 16 blocks over M=1024
    int bn = blockIdx.y * GTN;           // 8 blocks over N=256
    int tid = threadIdx.x;               // 256

    int tm = (tid & 15) * 4;             // 0..60
    int tn = (tid >> 4) * 2;             // 0..30

    float acc[4][2] = {};

    for (int k0 = 0; k0 < DD; k0 += GTK) {
#pragma unroll
        for (int i = 0; i < 2; i++) {
            int idx = tid + i * 256;
            int lr = idx >> 3;           // 0..63
            int lk = (idx & 7) * 4;      // 0..28
            float4 av = *(const float4*)&g_vn_pre[(size_t)(bm + lr) * DD + k0 + lk];
            As[lk + 0][lr] = av.x; As[lk + 1][lr] = av.y;
            As[lk + 2][lr] = av.z; As[lk + 3][lr] = av.w;
        }
        {
            int lr = tid >> 3;           // 0..31
            int lk = (tid & 7) * 4;
            float4 wv = *(const float4*)&W[(size_t)(bn + lr) * DD + k0 + lk];
            Ws[lk + 0][lr] = wv.x; Ws[lk + 1][lr] = wv.y;
            Ws[lk + 2][lr] = wv.z; Ws[lk + 3][lr] = wv.w;
        }
        __syncthreads();

#pragma unroll
        for (int k = 0; k < GTK; k++) {
            float4 a = *(const float4*)&As[k][tm];
            float2 w = *(const float2*)&Ws[k][tn];
            acc[0][0] += a.x * w.x; acc[0][1] += a.x * w.y;
            acc[1][0] += a.y * w.x; acc[1][1] += a.y * w.y;
            acc[2][0] += a.z * w.x; acc[2][1] += a.z * w.y;
            acc[3][0] += a.w * w.x; acc[3][1] += a.w * w.y;
        }
        __syncthreads();
    }

    float b0 = bias[bn + tn], b1 = bias[bn + tn + 1];
#pragma unroll
    for (int i = 0; i < 4; i++) {
        float2 o;
        o.x = acc[i][0] + b0;
        o.y = acc[i][1] + b1;
        *(float2*)&vn_out[(size_t)(bm + tm + i) * DD + bn + tn] = o;
    }
}

// ---------------------------------------------------------------------------
// K3: x_out = x + vn[batch].  One float4 per thread. x/out are single-use:
// stream them (.cs) so the vn gather (1 MB) stays cache-resident.
// ---------------------------------------------------------------------------
__global__ void k_add(const float* __restrict__ x,
                      const int* __restrict__ batch,
                      const float* __restrict__ vn,
                      float* __restrict__ out) {
    size_t i = (size_t)blockIdx.x * blockDim.x + threadIdx.x;  // float4 index
    int row = (int)(i >> 6);   // 64 float4 per 256-float row
    int c4  = (int)(i & 63);
    int b = batch[row];
    float4 xv = __ldcs((const float4*)x + i);
    float4 vv = __ldg((const float4*)vn + (size_t)b * 64 + c4);
    xv.x += vv.x; xv.y += vv.y; xv.z += vv.z; xv.w += vv.w;
    __stcs((float4*)out + i, xv);
}

// ---------------------------------------------------------------------------
extern "C" void kernel_launch(void* const* d_in, const int* in_sizes, int n_in,
                              void* d_out, int out_size) {
    const float* x     = (const float*)d_in[0];   // [N, D]
    const int*   batch = (const int*)d_in[1];     // [N]
    const float* W     = (const float*)d_in[2];   // [D, D]
    const float* bias  = (const float*)d_in[3];   // [D]
    // d_in[4] = layer_idx, unused

    int n = in_sizes[1];                          // number of nodes
    float* out    = (float*)d_out;                // x_out at [0, N*D)
    float* vn_out = out + (size_t)n * DD;         // vn at [N*D, N*D + B*D)

    k_pool<<<BB, 256>>>(x, batch, n);
    k_gemm<<<dim3(16, 8), 256>>>(W, bias, vn_out);
    int n4blocks = (int)(((size_t)n * 64 + 255) / 256);
    k_add <<<n4blocks, 256>>>(x, batch, vn_out, out);
}